// round 3
// baseline (speedup 1.0000x reference)
#include <cuda_runtime.h>
#include <cstdint>

#define BATCH   16
#define NPTS    4096
#define CIN     64
#define NPOINT  1024
#define NSAMPLE 32
#define R_TOTAL (BATCH*NPOINT*NSAMPLE)   // 524288 rows

// ---------------- device scratch (no allocations allowed) ----------------
__device__ float g_new_xyz[BATCH*NPOINT*3];
__device__ int   g_gidx[BATCH*NPOINT*NSAMPLE];
__device__ float g_bufA[(size_t)128*R_TOTAL];   // 268 MB
__device__ float g_bufB[(size_t)128*R_TOTAL];   // 268 MB
__device__ float g_sums[256];                   // [0:128)=sum, [128:256)=sumsq
__device__ float g_scale[128];
__device__ float g_shift[128];

// ---------------- FPS: one block per batch, 512 thr, 8 pts/thr ----------------
__global__ __launch_bounds__(512) void fps_kernel(const float* __restrict__ xyz,
                                                  float* __restrict__ d_out)
{
    const int b   = blockIdx.x;
    const int tid = threadIdx.x;
    const int lane = tid & 31, wid = tid >> 5;
    const float* xb = xyz + (size_t)b*NPTS*3;

    float px[8], py[8], pz[8], dst[8];
#pragma unroll
    for (int j = 0; j < 8; j++) {
        int n = tid*8 + j;
        px[j] = xb[n*3+0]; py[j] = xb[n*3+1]; pz[j] = xb[n*3+2];
        dst[j] = 1e10f;
    }

    __shared__ float s_v[16], s_x[16], s_y[16], s_z[16];
    __shared__ int   s_i[16];
    __shared__ float s_cen[3];
    if (tid == 0) { s_cen[0] = px[0]; s_cen[1] = py[0]; s_cen[2] = pz[0]; }
    __syncthreads();

    float* nxo = d_out    + (size_t)b*NPOINT*3;
    float* nxg = g_new_xyz + (size_t)b*NPOINT*3;

    for (int i = 0; i < NPOINT; i++) {
        const float cx = s_cen[0], cy = s_cen[1], cz = s_cen[2];
        if (tid == 0) {
            nxo[i*3+0] = cx; nxo[i*3+1] = cy; nxo[i*3+2] = cz;
            nxg[i*3+0] = cx; nxg[i*3+1] = cy; nxg[i*3+2] = cz;
        }
        // update distances; local argmax (first-index on ties via ascending scan)
        float bv = -1.0f, bx = 0.f, by = 0.f, bz = 0.f; int bi = 0;
#pragma unroll
        for (int j = 0; j < 8; j++) {
            float dx = __fsub_rn(px[j], cx);
            float dy = __fsub_rn(py[j], cy);
            float dz = __fsub_rn(pz[j], cz);
            // match reference summation order, NO fma contraction:
            float d  = __fadd_rn(__fadd_rn(__fmul_rn(dx,dx), __fmul_rn(dy,dy)), __fmul_rn(dz,dz));
            float nd = fminf(dst[j], d);
            dst[j] = nd;
            if (nd > bv) { bv = nd; bi = tid*8 + j; bx = px[j]; by = py[j]; bz = pz[j]; }
        }
        // warp argmax (tie -> lowest index)
#pragma unroll
        for (int off = 16; off; off >>= 1) {
            float ov = __shfl_down_sync(0xffffffffu, bv, off);
            int   oi = __shfl_down_sync(0xffffffffu, bi, off);
            float ox = __shfl_down_sync(0xffffffffu, bx, off);
            float oy = __shfl_down_sync(0xffffffffu, by, off);
            float oz = __shfl_down_sync(0xffffffffu, bz, off);
            if (ov > bv || (ov == bv && oi < bi)) { bv=ov; bi=oi; bx=ox; by=oy; bz=oz; }
        }
        if (lane == 0) { s_v[wid]=bv; s_i[wid]=bi; s_x[wid]=bx; s_y[wid]=by; s_z[wid]=bz; }
        __syncthreads();
        if (wid == 0) {
            bv = (lane < 16) ? s_v[lane] : -1.0f;
            bi = (lane < 16) ? s_i[lane] : 0x7fffffff;
            bx = s_x[lane & 15]; by = s_y[lane & 15]; bz = s_z[lane & 15];
#pragma unroll
            for (int off = 8; off; off >>= 1) {
                float ov = __shfl_down_sync(0xffffffffu, bv, off);
                int   oi = __shfl_down_sync(0xffffffffu, bi, off);
                float ox = __shfl_down_sync(0xffffffffu, bx, off);
                float oy = __shfl_down_sync(0xffffffffu, by, off);
                float oz = __shfl_down_sync(0xffffffffu, bz, off);
                if (ov > bv || (ov == bv && oi < bi)) { bv=ov; bi=oi; bx=ox; by=oy; bz=oz; }
            }
            if (lane == 0) { s_cen[0]=bx; s_cen[1]=by; s_cen[2]=bz; }
        }
        __syncthreads();
    }
}

// ---------------- ball query: one warp per center ----------------
__global__ __launch_bounds__(128) void ballquery_kernel(const float* __restrict__ xyz)
{
    const int wg   = (blockIdx.x * blockDim.x + threadIdx.x) >> 5;  // center id
    const int lane = threadIdx.x & 31;
    if (wg >= BATCH*NPOINT) return;
    const int b = wg >> 10;
    const float* xb = xyz + (size_t)b*NPTS*3;

    const float cx = g_new_xyz[wg*3+0];
    const float cy = g_new_xyz[wg*3+1];
    const float cz = g_new_xyz[wg*3+2];
    const float sc = __fadd_rn(__fadd_rn(__fmul_rn(cx,cx), __fmul_rn(cy,cy)), __fmul_rn(cz,cz));
    const float TH = (float)(0.9*0.9);   // ref compares sqrt(d2) > radius**2 (!)

    int* gout = g_gidx + (size_t)wg*NSAMPLE;
    int cnt = 0;
    int first_idx = 0;
    bool have_first = false;

    for (int base = 0; base < NPTS; base += 32) {
        const int n = base + lane;
        float x = xb[n*3+0], y = xb[n*3+1], z = xb[n*3+2];
        float sp  = __fadd_rn(__fadd_rn(__fmul_rn(x,x), __fmul_rn(y,y)), __fmul_rn(z,z));
        float dot = __fadd_rn(__fadd_rn(__fmul_rn(cx,x), __fmul_rn(cy,y)), __fmul_rn(cz,z));
        float d2  = __fsub_rn(__fadd_rn(sc, sp), __fmul_rn(2.0f, dot));
        float dist = __fsqrt_rn(fmaxf(d2, 0.0f));
        bool in = !(dist > TH);
        unsigned bits = __ballot_sync(0xffffffffu, in);
        if (!have_first && bits) { first_idx = base + __ffs((int)bits) - 1; have_first = true; }
        if (in) {
            int pos = cnt + __popc(bits & ((1u << lane) - 1u));
            if (pos < NSAMPLE) gout[pos] = n;
        }
        cnt += __popc(bits);
        if (cnt >= NSAMPLE) break;
    }
    if (cnt < NSAMPLE) {
        for (int pos = cnt + lane; pos < NSAMPLE; pos += 32) gout[pos] = first_idx;
    }
}

// ---------------- layer0: gather + concat + linear (IC=67, OC=64) ----------------
__global__ __launch_bounds__(256) void layer0_kernel(const float* __restrict__ xyz,
                                                     const float* __restrict__ points,
                                                     const float* __restrict__ w,
                                                     const float* __restrict__ bias,
                                                     float* __restrict__ y)
{
    __shared__ float sw[64*67];
    __shared__ float sb[64];
    for (int i = threadIdx.x; i < 64*67; i += 256) sw[i] = w[i];
    if (threadIdx.x < 64) sb[threadIdx.x] = bias[threadIdx.x];
    __syncthreads();

    const int r = blockIdx.x*256 + threadIdx.x;
    const int center = r >> 5;
    const int b = center >> 10;
    const int n = g_gidx[r];
    const float* pp = points + ((size_t)(b*NPTS + n))*CIN;
    const float x0 = xyz[(size_t)(b*NPTS+n)*3+0] - g_new_xyz[center*3+0];
    const float x1 = xyz[(size_t)(b*NPTS+n)*3+1] - g_new_xyz[center*3+1];
    const float x2 = xyz[(size_t)(b*NPTS+n)*3+2] - g_new_xyz[center*3+2];

#pragma unroll 1
    for (int ocb = 0; ocb < 64; ocb += 16) {
        float acc[16];
#pragma unroll
        for (int j = 0; j < 16; j++) {
            const float* wr = sw + (ocb+j)*67;
            float a = sb[ocb+j];
            a = fmaf(wr[0], x0, a);
            a = fmaf(wr[1], x1, a);
            a = fmaf(wr[2], x2, a);
            acc[j] = a;
        }
#pragma unroll 4
        for (int c = 0; c < CIN; c++) {
            float xc = pp[c];
#pragma unroll
            for (int j = 0; j < 16; j++)
                acc[j] = fmaf(sw[(ocb+j)*67 + 3 + c], xc, acc[j]);
        }
#pragma unroll
        for (int j = 0; j < 16; j++)
            y[(size_t)(ocb+j)*R_TOTAL + r] = acc[j];
    }
}

// ---------------- generic layer: normalize(prev BN)+relu input, linear ----------------
template<int IC, int OC>
__global__ __launch_bounds__(256) void mlp_layer_kernel(const float* __restrict__ x,
                                                        const float* __restrict__ w,
                                                        const float* __restrict__ bias,
                                                        float* __restrict__ y)
{
    __shared__ float sw[OC*IC];
    __shared__ float sb[OC];
    __shared__ float ssc[IC], ssh[IC];
    for (int i = threadIdx.x; i < OC*IC; i += 256) sw[i] = w[i];
    if (threadIdx.x < OC) sb[threadIdx.x] = bias[threadIdx.x];
    if (threadIdx.x < IC) { ssc[threadIdx.x] = g_scale[threadIdx.x]; ssh[threadIdx.x] = g_shift[threadIdx.x]; }
    __syncthreads();

    const int r = blockIdx.x*256 + threadIdx.x;
    const float* xr = x + r;

#pragma unroll 1
    for (int ocb = 0; ocb < OC; ocb += 16) {
        float acc[16];
#pragma unroll
        for (int j = 0; j < 16; j++) acc[j] = sb[ocb+j];
#pragma unroll 4
        for (int c = 0; c < IC; c++) {
            float xc = xr[(size_t)c*R_TOTAL];
            xc = fmaxf(fmaf(xc, ssc[c], ssh[c]), 0.0f);
#pragma unroll
            for (int j = 0; j < 16; j++)
                acc[j] = fmaf(sw[(ocb+j)*IC + c], xc, acc[j]);
        }
#pragma unroll
        for (int j = 0; j < 16; j++)
            y[(size_t)(ocb+j)*R_TOTAL + r] = acc[j];
    }
}

// ---------------- BN stats: grid (slabs, channels) ----------------
__global__ __launch_bounds__(256) void stats_kernel(const float* __restrict__ y)
{
    const int c = blockIdx.y;
    const float* p = y + (size_t)c*R_TOTAL;
    float s = 0.f, ss = 0.f;
    for (int i = blockIdx.x*256 + threadIdx.x; i < R_TOTAL; i += gridDim.x*256) {
        float v = p[i];
        s += v;
        ss = fmaf(v, v, ss);
    }
#pragma unroll
    for (int off = 16; off; off >>= 1) {
        s  += __shfl_down_sync(0xffffffffu, s,  off);
        ss += __shfl_down_sync(0xffffffffu, ss, off);
    }
    __shared__ float sh[16];
    const int lane = threadIdx.x & 31, wid = threadIdx.x >> 5;
    if (lane == 0) { sh[wid] = s; sh[8 + wid] = ss; }
    __syncthreads();
    if (threadIdx.x == 0) {
        float ts = 0.f, tss = 0.f;
#pragma unroll
        for (int k = 0; k < 8; k++) { ts += sh[k]; tss += sh[8+k]; }
        atomicAdd(&g_sums[c], ts);
        atomicAdd(&g_sums[128 + c], tss);
    }
}

// ---------------- finalize BN: scale/shift, reset sums ----------------
__global__ void finalize_kernel(const float* __restrict__ gamma,
                                const float* __restrict__ beta, int OC)
{
    const int c = threadIdx.x;   // 128 threads
    const float s  = g_sums[c];
    const float ss = g_sums[128 + c];
    if (c < OC) {
        const float inv = 1.0f / (float)R_TOTAL;
        float mu  = s * inv;
        float var = ss * inv - mu*mu;
        float sc  = gamma[c] / sqrtf(var + 1e-5f);
        g_scale[c] = sc;
        g_shift[c] = fmaf(-mu, sc, beta[c]);
    }
    g_sums[c] = 0.f;
    g_sums[128 + c] = 0.f;
}

// ---------------- final: normalize + relu + maxpool over k ----------------
__global__ __launch_bounds__(256) void final_kernel(const float* __restrict__ y,
                                                    float* __restrict__ out)
{
    const int idx = blockIdx.x*256 + threadIdx.x;     // B*NPOINT*128
    const int oc = idx & 127;
    const int center = idx >> 7;
    const float* p = y + (size_t)oc*R_TOTAL + (size_t)center*NSAMPLE;
    const float sc = g_scale[oc], sh = g_shift[oc];
    float m = 0.0f;   // relu outputs are >= 0
#pragma unroll
    for (int k = 0; k < NSAMPLE; k++) {
        float v = fmaxf(fmaf(p[k], sc, sh), 0.0f);
        m = fmaxf(m, v);
    }
    out[(size_t)BATCH*NPOINT*3 + idx] = m;
}

// ---------------- launcher ----------------
extern "C" void kernel_launch(void* const* d_in, const int* in_sizes, int n_in,
                              void* d_out, int out_size)
{
    (void)in_sizes; (void)n_in; (void)out_size;
    const float* xyz    = (const float*)d_in[0];
    const float* points = (const float*)d_in[1];
    const float* w0  = (const float*)d_in[2];
    const float* b0  = (const float*)d_in[3];
    const float* gm0 = (const float*)d_in[4];
    const float* bt0 = (const float*)d_in[5];
    const float* w1  = (const float*)d_in[6];
    const float* b1  = (const float*)d_in[7];
    const float* gm1 = (const float*)d_in[8];
    const float* bt1 = (const float*)d_in[9];
    const float* w2  = (const float*)d_in[10];
    const float* b2  = (const float*)d_in[11];
    const float* gm2 = (const float*)d_in[12];
    const float* bt2 = (const float*)d_in[13];
    float* out = (float*)d_out;

    float *bufA = nullptr, *bufB = nullptr;
    cudaGetSymbolAddress((void**)&bufA, g_bufA);
    cudaGetSymbolAddress((void**)&bufB, g_bufB);

    fps_kernel<<<BATCH, 512>>>(xyz, out);
    ballquery_kernel<<<(BATCH*NPOINT)/4, 128>>>(xyz);

    layer0_kernel<<<R_TOTAL/256, 256>>>(xyz, points, w0, b0, bufA);
    stats_kernel<<<dim3(64, 64), 256>>>(bufA);
    finalize_kernel<<<1, 128>>>(gm0, bt0, 64);

    mlp_layer_kernel<64,64><<<R_TOTAL/256, 256>>>(bufA, w1, b1, bufB);
    stats_kernel<<<dim3(64, 64), 256>>>(bufB);
    finalize_kernel<<<1, 128>>>(gm1, bt1, 64);

    mlp_layer_kernel<64,128><<<R_TOTAL/256, 256>>>(bufB, w2, b2, bufA);
    stats_kernel<<<dim3(64, 128), 256>>>(bufA);
    finalize_kernel<<<1, 128>>>(gm2, bt2, 128);

    final_kernel<<<(BATCH*NPOINT*128)/256, 256>>>(bufA, out);
}

// round 4
// speedup vs baseline: 1.3675x; 1.3675x over previous
#include <cuda_runtime.h>
#include <cstdint>

#define BATCH   16
#define NPTS    4096
#define CIN     64
#define NPOINT  1024
#define NSAMPLE 32
#define R_TOTAL (BATCH*NPOINT*NSAMPLE)   // 524288 rows
#define RPAIRS  (R_TOTAL/2)

typedef unsigned long long u64;

// ---------------- device scratch (no allocations allowed) ----------------
__device__ float g_new_xyz[BATCH*NPOINT*3];
__device__ int   g_gidx[BATCH*NPOINT*NSAMPLE];
__device__ float g_bufA[(size_t)128*R_TOTAL];   // 268 MB
__device__ float g_bufB[(size_t)128*R_TOTAL];   // 268 MB
__device__ float g_sums[256];                   // [0:128)=sum, [128:256)=sumsq
__device__ float g_scale[128];
__device__ float g_shift[128];

// ---------------- f32x2 helpers ----------------
__device__ __forceinline__ u64 pack2(float lo, float hi) {
    u64 r; asm("mov.b64 %0, {%1, %2};" : "=l"(r) : "f"(lo), "f"(hi)); return r;
}
__device__ __forceinline__ void unpack2(u64 v, float& lo, float& hi) {
    asm("mov.b64 {%0, %1}, %2;" : "=f"(lo), "=f"(hi) : "l"(v));
}
__device__ __forceinline__ void fma2(u64& d, u64 a, u64 b) {
    asm("fma.rn.f32x2 %0, %1, %2, %0;" : "+l"(d) : "l"(a), "l"(b));
}
__device__ __forceinline__ u64 umax64(u64 a, u64 b) { return a > b ? a : b; }

// ---------------- FPS: one block per batch, 512 thr, 8 pts/thr ----------------
// Packed argmax key: (float_bits(dist) << 32) | ~idx.  dist >= 0 so float bits
// are order-preserving; ~idx makes ties resolve to the LOWEST index (matches
// jnp.argmax). Distance arithmetic is kept bit-exact to the reference
// (rn mul/add, no FMA contraction).
__global__ __launch_bounds__(512) void fps_kernel(const float* __restrict__ xyz,
                                                  float* __restrict__ d_out)
{
    const int b   = blockIdx.x;
    const int tid = threadIdx.x;
    const int lane = tid & 31, wid = tid >> 5;
    const float* xb = xyz + (size_t)b*NPTS*3;

    float px[8], py[8], pz[8], dst[8];
#pragma unroll
    for (int j = 0; j < 8; j++) {
        int n = tid*8 + j;
        px[j] = xb[n*3+0]; py[j] = xb[n*3+1]; pz[j] = xb[n*3+2];
        dst[j] = 1e10f;
    }

    __shared__ u64   s_k[16];
    __shared__ float s_cen[3];
    if (tid == 0) { s_cen[0] = px[0]; s_cen[1] = py[0]; s_cen[2] = pz[0]; }
    __syncthreads();

    float* nxo = d_out     + (size_t)b*NPOINT*3;
    float* nxg = g_new_xyz + (size_t)b*NPOINT*3;

    for (int i = 0; i < NPOINT; i++) {
        const float cx = s_cen[0], cy = s_cen[1], cz = s_cen[2];
        if (tid == 0) {
            nxo[i*3+0] = cx; nxo[i*3+1] = cy; nxo[i*3+2] = cz;
            nxg[i*3+0] = cx; nxg[i*3+1] = cy; nxg[i*3+2] = cz;
        }
        u64 bk = 0;
#pragma unroll
        for (int j = 0; j < 8; j++) {
            float dx = __fsub_rn(px[j], cx);
            float dy = __fsub_rn(py[j], cy);
            float dz = __fsub_rn(pz[j], cz);
            float d  = __fadd_rn(__fadd_rn(__fmul_rn(dx,dx), __fmul_rn(dy,dy)), __fmul_rn(dz,dz));
            float nd = fminf(dst[j], d);
            dst[j] = nd;
            u64 k;
            asm("mov.b64 %0, {%1, %2};" : "=l"(k)
                : "r"(~(tid*8+j)), "r"(__float_as_uint(nd)));
            bk = umax64(bk, k);
        }
#pragma unroll
        for (int off = 16; off; off >>= 1)
            bk = umax64(bk, __shfl_down_sync(0xffffffffu, bk, off));
        if (lane == 0) s_k[wid] = bk;
        __syncthreads();
        if (wid == 0) {
            bk = (lane < 16) ? s_k[lane] : 0ull;
#pragma unroll
            for (int off = 8; off; off >>= 1)
                bk = umax64(bk, __shfl_down_sync(0xffffffffu, bk, off));
            if (lane == 0) {
                int win = ~((int)(unsigned)(bk & 0xffffffffull));
                const float* cp = xb + (size_t)win*3;
                s_cen[0] = cp[0]; s_cen[1] = cp[1]; s_cen[2] = cp[2];
            }
        }
        __syncthreads();
    }
}

// ---------------- ball query: one warp per center ----------------
__global__ __launch_bounds__(128) void ballquery_kernel(const float* __restrict__ xyz)
{
    const int wg   = (blockIdx.x * blockDim.x + threadIdx.x) >> 5;  // center id
    const int lane = threadIdx.x & 31;
    if (wg >= BATCH*NPOINT) return;
    const int b = wg >> 10;
    const float* xb = xyz + (size_t)b*NPTS*3;

    const float cx = g_new_xyz[wg*3+0];
    const float cy = g_new_xyz[wg*3+1];
    const float cz = g_new_xyz[wg*3+2];
    const float sc = __fadd_rn(__fadd_rn(__fmul_rn(cx,cx), __fmul_rn(cy,cy)), __fmul_rn(cz,cz));
    const float TH = (float)(0.9*0.9);   // ref compares sqrt(d2) > radius**2 (!)

    int* gout = g_gidx + (size_t)wg*NSAMPLE;
    int cnt = 0;
    int first_idx = 0;
    bool have_first = false;

    for (int base = 0; base < NPTS; base += 32) {
        const int n = base + lane;
        float x = xb[n*3+0], y = xb[n*3+1], z = xb[n*3+2];
        float sp  = __fadd_rn(__fadd_rn(__fmul_rn(x,x), __fmul_rn(y,y)), __fmul_rn(z,z));
        float dot = __fadd_rn(__fadd_rn(__fmul_rn(cx,x), __fmul_rn(cy,y)), __fmul_rn(cz,z));
        float d2  = __fsub_rn(__fadd_rn(sc, sp), __fmul_rn(2.0f, dot));
        float dist = __fsqrt_rn(fmaxf(d2, 0.0f));
        bool in = !(dist > TH);
        unsigned bits = __ballot_sync(0xffffffffu, in);
        if (!have_first && bits) { first_idx = base + __ffs((int)bits) - 1; have_first = true; }
        if (in) {
            int pos = cnt + __popc(bits & ((1u << lane) - 1u));
            if (pos < NSAMPLE) gout[pos] = n;
        }
        cnt += __popc(bits);
        if (cnt >= NSAMPLE) break;
    }
    if (cnt < NSAMPLE) {
        for (int pos = cnt + lane; pos < NSAMPLE; pos += 32) gout[pos] = first_idx;
    }
}

// ---------------- layer0: gather + concat + linear (IC=67, OC=64), f32x2 ----------------
// Each thread owns row pair (2t, 2t+1); all 64 output accumulators in regs.
__global__ __launch_bounds__(256) void layer0_kernel(const float* __restrict__ xyz,
                                                     const float* __restrict__ points,
                                                     const float* __restrict__ w,
                                                     const float* __restrict__ bias,
                                                     float* __restrict__ y)
{
    __shared__ u64   sw2[64*64];   // [c][oc], weight duplicated into both halves
    __shared__ float sw3[3*64];    // first 3 input channels (rel xyz), scalar
    __shared__ float sb[64];
    for (int i = threadIdx.x; i < 64*64; i += 256) {
        int c = i >> 6, oc = i & 63;
        float v = w[oc*67 + 3 + c];
        sw2[i] = pack2(v, v);
    }
    if (threadIdx.x < 3*64) {
        int k = threadIdx.x >> 6, oc = threadIdx.x & 63;
        sw3[threadIdx.x] = w[oc*67 + k];
    }
    if (threadIdx.x < 64) sb[threadIdx.x] = bias[threadIdx.x];
    __syncthreads();

    const int p  = blockIdx.x*256 + threadIdx.x;   // pair index
    const int r0 = p*2, r1 = r0 + 1;
    const int center = r0 >> 5;
    const int b = center >> 10;
    const int n0 = g_gidx[r0];
    const int n1 = g_gidx[r1];
    const float* pp0 = points + ((size_t)(b*NPTS + n0))*CIN;
    const float* pp1 = points + ((size_t)(b*NPTS + n1))*CIN;
    const float cx = g_new_xyz[center*3+0];
    const float cy = g_new_xyz[center*3+1];
    const float cz = g_new_xyz[center*3+2];
    const float x0a = xyz[(size_t)(b*NPTS+n0)*3+0] - cx;
    const float x1a = xyz[(size_t)(b*NPTS+n0)*3+1] - cy;
    const float x2a = xyz[(size_t)(b*NPTS+n0)*3+2] - cz;
    const float x0b = xyz[(size_t)(b*NPTS+n1)*3+0] - cx;
    const float x1b = xyz[(size_t)(b*NPTS+n1)*3+1] - cy;
    const float x2b = xyz[(size_t)(b*NPTS+n1)*3+2] - cz;

    u64 acc[64];
#pragma unroll
    for (int j = 0; j < 64; j++) {
        float a = sb[j], bvl = sb[j];
        a   = fmaf(sw3[j],       x0a, a);
        a   = fmaf(sw3[64+j],    x1a, a);
        a   = fmaf(sw3[128+j],   x2a, a);
        bvl = fmaf(sw3[j],       x0b, bvl);
        bvl = fmaf(sw3[64+j],    x1b, bvl);
        bvl = fmaf(sw3[128+j],   x2b, bvl);
        acc[j] = pack2(a, bvl);
    }

    float a0 = pp0[0], a1 = pp1[0];
#pragma unroll 1
    for (int c = 0; c < CIN; c++) {
        int cn = (c + 1 < CIN) ? c + 1 : c;
        float na0 = pp0[cn], na1 = pp1[cn];
        u64 xa = pack2(a0, a1);
        const ulonglong2* wrow = (const ulonglong2*)(sw2 + c*64);
#pragma unroll
        for (int q = 0; q < 32; q++) {
            ulonglong2 wv = wrow[q];
            fma2(acc[2*q],   wv.x, xa);
            fma2(acc[2*q+1], wv.y, xa);
        }
        a0 = na0; a1 = na1;
    }
#pragma unroll
    for (int j = 0; j < 64; j++) {
        float lo, hi; unpack2(acc[j], lo, hi);
        ((float2*)(y + (size_t)j*R_TOTAL))[p] = make_float2(lo, hi);
    }
}

// ---------------- generic layer: BN(prev)+relu input, linear, f32x2 ----------------
template<int IC>
__global__ __launch_bounds__(256) void mlp_layer_kernel(const float* __restrict__ x,
                                                        const float* __restrict__ w,
                                                        const float* __restrict__ bias,
                                                        float* __restrict__ y)
{
    __shared__ u64   sw2[IC*64];   // [c][oc] packed duplicated weights
    __shared__ float sb[64];
    __shared__ float ssc[IC], ssh[IC];
    const int ocb = blockIdx.y * 64;
    for (int i = threadIdx.x; i < IC*64; i += 256) {
        int c = i >> 6, oc = i & 63;
        float v = w[(ocb + oc)*IC + c];
        sw2[i] = pack2(v, v);
    }
    if (threadIdx.x < 64) sb[threadIdx.x] = bias[ocb + threadIdx.x];
    if (threadIdx.x < IC) { ssc[threadIdx.x] = g_scale[threadIdx.x]; ssh[threadIdx.x] = g_shift[threadIdx.x]; }
    __syncthreads();

    const int p = blockIdx.x*256 + threadIdx.x;    // pair index
    const float2* x2 = (const float2*)x;

    u64 acc[64];
#pragma unroll
    for (int j = 0; j < 64; j++) acc[j] = pack2(sb[j], sb[j]);

    float2 cur = x2[p];
#pragma unroll 1
    for (int c = 0; c < IC; c++) {
        int cn = (c + 1 < IC) ? c + 1 : c;
        float2 nxt = x2[(size_t)cn*RPAIRS + p];
        float s = ssc[c], h = ssh[c];
        float a0 = fmaxf(fmaf(cur.x, s, h), 0.0f);
        float a1 = fmaxf(fmaf(cur.y, s, h), 0.0f);
        u64 xa = pack2(a0, a1);
        const ulonglong2* wrow = (const ulonglong2*)(sw2 + c*64);
#pragma unroll
        for (int q = 0; q < 32; q++) {
            ulonglong2 wv = wrow[q];
            fma2(acc[2*q],   wv.x, xa);
            fma2(acc[2*q+1], wv.y, xa);
        }
        cur = nxt;
    }
#pragma unroll
    for (int j = 0; j < 64; j++) {
        float lo, hi; unpack2(acc[j], lo, hi);
        ((float2*)(y + (size_t)(ocb + j)*R_TOTAL))[p] = make_float2(lo, hi);
    }
}

// ---------------- BN stats: float4 grid-stride, grid (slabs, channels) ----------------
__global__ __launch_bounds__(256) void stats_kernel(const float* __restrict__ y)
{
    const int c = blockIdx.y;
    const float4* p = (const float4*)(y + (size_t)c*R_TOTAL);
    const int n4 = R_TOTAL / 4;
    float s = 0.f, ss = 0.f;
    for (int i = blockIdx.x*256 + threadIdx.x; i < n4; i += gridDim.x*256) {
        float4 v = p[i];
        s += v.x; ss = fmaf(v.x, v.x, ss);
        s += v.y; ss = fmaf(v.y, v.y, ss);
        s += v.z; ss = fmaf(v.z, v.z, ss);
        s += v.w; ss = fmaf(v.w, v.w, ss);
    }
#pragma unroll
    for (int off = 16; off; off >>= 1) {
        s  += __shfl_down_sync(0xffffffffu, s,  off);
        ss += __shfl_down_sync(0xffffffffu, ss, off);
    }
    __shared__ float sh[16];
    const int lane = threadIdx.x & 31, wid = threadIdx.x >> 5;
    if (lane == 0) { sh[wid] = s; sh[8 + wid] = ss; }
    __syncthreads();
    if (threadIdx.x == 0) {
        float ts = 0.f, tss = 0.f;
#pragma unroll
        for (int k = 0; k < 8; k++) { ts += sh[k]; tss += sh[8+k]; }
        atomicAdd(&g_sums[c], ts);
        atomicAdd(&g_sums[128 + c], tss);
    }
}

// ---------------- finalize BN: scale/shift, reset sums ----------------
__global__ void finalize_kernel(const float* __restrict__ gamma,
                                const float* __restrict__ beta, int OC)
{
    const int c = threadIdx.x;   // 128 threads
    const float s  = g_sums[c];
    const float ss = g_sums[128 + c];
    if (c < OC) {
        const float inv = 1.0f / (float)R_TOTAL;
        float mu  = s * inv;
        float var = ss * inv - mu*mu;
        float sc  = gamma[c] / sqrtf(var + 1e-5f);
        g_scale[c] = sc;
        g_shift[c] = fmaf(-mu, sc, beta[c]);
    }
    g_sums[c] = 0.f;
    g_sums[128 + c] = 0.f;
}

// ---------------- final: normalize + relu + maxpool over k (float4) ----------------
__global__ __launch_bounds__(256) void final_kernel(const float* __restrict__ y,
                                                    float* __restrict__ out)
{
    const int idx = blockIdx.x*256 + threadIdx.x;     // B*NPOINT*128
    const int oc = idx & 127;
    const int center = idx >> 7;
    const float4* p = (const float4*)(y + (size_t)oc*R_TOTAL + (size_t)center*NSAMPLE);
    const float sc = g_scale[oc], sh = g_shift[oc];
    float m = 0.0f;   // relu outputs are >= 0
#pragma unroll
    for (int k = 0; k < NSAMPLE/4; k++) {
        float4 v = p[k];
        m = fmaxf(m, fmaf(v.x, sc, sh));
        m = fmaxf(m, fmaf(v.y, sc, sh));
        m = fmaxf(m, fmaf(v.z, sc, sh));
        m = fmaxf(m, fmaf(v.w, sc, sh));
    }
    out[(size_t)BATCH*NPOINT*3 + idx] = fmaxf(m, 0.0f);
}

// ---------------- launcher ----------------
extern "C" void kernel_launch(void* const* d_in, const int* in_sizes, int n_in,
                              void* d_out, int out_size)
{
    (void)in_sizes; (void)n_in; (void)out_size;
    const float* xyz    = (const float*)d_in[0];
    const float* points = (const float*)d_in[1];
    const float* w0  = (const float*)d_in[2];
    const float* b0  = (const float*)d_in[3];
    const float* gm0 = (const float*)d_in[4];
    const float* bt0 = (const float*)d_in[5];
    const float* w1  = (const float*)d_in[6];
    const float* b1  = (const float*)d_in[7];
    const float* gm1 = (const float*)d_in[8];
    const float* bt1 = (const float*)d_in[9];
    const float* w2  = (const float*)d_in[10];
    const float* b2  = (const float*)d_in[11];
    const float* gm2 = (const float*)d_in[12];
    const float* bt2 = (const float*)d_in[13];
    float* out = (float*)d_out;

    float *bufA = nullptr, *bufB = nullptr;
    cudaGetSymbolAddress((void**)&bufA, g_bufA);
    cudaGetSymbolAddress((void**)&bufB, g_bufB);

    fps_kernel<<<BATCH, 512>>>(xyz, out);
    ballquery_kernel<<<(BATCH*NPOINT)/4, 128>>>(xyz);

    layer0_kernel<<<RPAIRS/256, 256>>>(xyz, points, w0, b0, bufA);
    stats_kernel<<<dim3(32, 64), 256>>>(bufA);
    finalize_kernel<<<1, 128>>>(gm0, bt0, 64);

    mlp_layer_kernel<64><<<dim3(RPAIRS/256, 1), 256>>>(bufA, w1, b1, bufB);
    stats_kernel<<<dim3(32, 64), 256>>>(bufB);
    finalize_kernel<<<1, 128>>>(gm1, bt1, 64);

    mlp_layer_kernel<64><<<dim3(RPAIRS/256, 2), 256>>>(bufB, w2, b2, bufA);
    stats_kernel<<<dim3(32, 128), 256>>>(bufA);
    finalize_kernel<<<1, 128>>>(gm2, bt2, 128);

    final_kernel<<<(BATCH*NPOINT*128)/256, 256>>>(bufA, out);
}

// round 5
// speedup vs baseline: 1.4931x; 1.0919x over previous
#include <cuda_runtime.h>
#include <cstdint>

#define BATCH   16
#define NPTS    4096
#define CIN     64
#define NPOINT  1024
#define NSAMPLE 32
#define R_TOTAL (BATCH*NPOINT*NSAMPLE)   // 524288 rows
#define RPAIRS  (R_TOTAL/2)
#define NCENT   (BATCH*NPOINT)           // 16384

typedef unsigned long long u64;

// ---------------- device scratch (no allocations allowed) ----------------
__device__ float g_new_xyz[BATCH*NPOINT*3];
__device__ int   g_gidx[BATCH*NPOINT*NSAMPLE];
__device__ float g_bufA[(size_t)64*R_TOTAL];    // 134 MB (layer0 out)
__device__ float g_bufB[(size_t)64*R_TOTAL];    // 134 MB (mlp1 out)
__device__ float g_pmax[(size_t)NCENT*128];     // 8 MB pooled raw max
__device__ float g_pmin[(size_t)NCENT*128];     // 8 MB pooled raw min
__device__ float g_sums[256];                   // [0:128)=sum, [128:256)=sumsq
__device__ float g_scale[128];
__device__ float g_shift[128];

// ---------------- f32x2 helpers ----------------
__device__ __forceinline__ u64 pack2(float lo, float hi) {
    u64 r; asm("mov.b64 %0, {%1, %2};" : "=l"(r) : "f"(lo), "f"(hi)); return r;
}
__device__ __forceinline__ void unpack2(u64 v, float& lo, float& hi) {
    asm("mov.b64 {%0, %1}, %2;" : "=f"(lo), "=f"(hi) : "l"(v));
}
__device__ __forceinline__ void fma2(u64& d, u64 a, u64 b) {
    asm("fma.rn.f32x2 %0, %1, %2, %0;" : "+l"(d) : "l"(a), "l"(b));
}
__device__ __forceinline__ u64 umax64(u64 a, u64 b) { return a > b ? a : b; }

// ---------------- FPS: one block per batch, 512 thr, 8 pts/thr --------------
// Key = (float_bits(dist) << 32) | ~idx  (dist >= 0 -> bits order-preserving;
// ~idx -> lowest index wins ties, matching jnp.argmax). Distance arithmetic
// bit-exact to reference (rn mul/add, no FMA contraction).
// ONE barrier per iteration: per-warp maxima go to a parity-double-buffered
// smem slot; after the barrier EVERY warp redundantly butterfly-reduces the
// 16 partials and loads the winning center's coords straight from xyz (L1).
__global__ __launch_bounds__(512) void fps_kernel(const float* __restrict__ xyz,
                                                  float* __restrict__ d_out)
{
    const int b   = blockIdx.x;
    const int tid = threadIdx.x;
    const int lane = tid & 31, wid = tid >> 5;
    const float* xb = xyz + (size_t)b*NPTS*3;

    float px[8], py[8], pz[8], dst[8];
#pragma unroll
    for (int j = 0; j < 8; j++) {
        int n = tid*8 + j;
        px[j] = xb[n*3+0]; py[j] = xb[n*3+1]; pz[j] = xb[n*3+2];
        dst[j] = 1e10f;
    }

    __shared__ u64 s_k[2][16];

    float cx = xb[0], cy = xb[1], cz = xb[2];   // first center = point 0

    float* nxo = d_out     + (size_t)b*NPOINT*3;
    float* nxg = g_new_xyz + (size_t)b*NPOINT*3;

    for (int i = 0; i < NPOINT; i++) {
        if (tid == 0) {
            nxo[i*3+0] = cx; nxo[i*3+1] = cy; nxo[i*3+2] = cz;
            nxg[i*3+0] = cx; nxg[i*3+1] = cy; nxg[i*3+2] = cz;
        }
        u64 k[8];
#pragma unroll
        for (int j = 0; j < 8; j++) {
            float dx = __fsub_rn(px[j], cx);
            float dy = __fsub_rn(py[j], cy);
            float dz = __fsub_rn(pz[j], cz);
            float d  = __fadd_rn(__fadd_rn(__fmul_rn(dx,dx), __fmul_rn(dy,dy)), __fmul_rn(dz,dz));
            float nd = fminf(dst[j], d);
            dst[j] = nd;
            asm("mov.b64 %0, {%1, %2};" : "=l"(k[j])
                : "r"(~(tid*8+j)), "r"(__float_as_uint(nd)));
        }
        // tree local max (ILP)
        u64 m01 = umax64(k[0], k[1]), m23 = umax64(k[2], k[3]);
        u64 m45 = umax64(k[4], k[5]), m67 = umax64(k[6], k[7]);
        u64 bk  = umax64(umax64(m01, m23), umax64(m45, m67));
        // warp reduce (5 levels)
#pragma unroll
        for (int off = 16; off; off >>= 1)
            bk = umax64(bk, __shfl_down_sync(0xffffffffu, bk, off));
        if (lane == 0) s_k[i & 1][wid] = bk;
        __syncthreads();
        // redundant final reduce in every warp (no 2nd barrier)
        u64 v = s_k[i & 1][lane & 15];
#pragma unroll
        for (int off = 8; off; off >>= 1)
            v = umax64(v, __shfl_xor_sync(0xffffffffu, v, off));
        int win = ~((int)(unsigned)(v & 0xffffffffull));
        cx = xb[win*3+0]; cy = xb[win*3+1]; cz = xb[win*3+2];
    }
}

// ---------------- ball query: one warp per center ----------------
__global__ __launch_bounds__(128) void ballquery_kernel(const float* __restrict__ xyz)
{
    const int wg   = (blockIdx.x * blockDim.x + threadIdx.x) >> 5;  // center id
    const int lane = threadIdx.x & 31;
    if (wg >= NCENT) return;
    const int b = wg >> 10;
    const float* xb = xyz + (size_t)b*NPTS*3;

    const float cx = g_new_xyz[wg*3+0];
    const float cy = g_new_xyz[wg*3+1];
    const float cz = g_new_xyz[wg*3+2];
    const float sc = __fadd_rn(__fadd_rn(__fmul_rn(cx,cx), __fmul_rn(cy,cy)), __fmul_rn(cz,cz));
    const float TH = (float)(0.9*0.9);   // ref compares sqrt(d2) > radius**2 (!)

    int* gout = g_gidx + (size_t)wg*NSAMPLE;
    int cnt = 0;
    int first_idx = 0;
    bool have_first = false;

    for (int base = 0; base < NPTS; base += 32) {
        const int n = base + lane;
        float x = xb[n*3+0], y = xb[n*3+1], z = xb[n*3+2];
        float sp  = __fadd_rn(__fadd_rn(__fmul_rn(x,x), __fmul_rn(y,y)), __fmul_rn(z,z));
        float dot = __fadd_rn(__fadd_rn(__fmul_rn(cx,x), __fmul_rn(cy,y)), __fmul_rn(cz,z));
        float d2  = __fsub_rn(__fadd_rn(sc, sp), __fmul_rn(2.0f, dot));
        float dist = __fsqrt_rn(fmaxf(d2, 0.0f));
        bool in = !(dist > TH);
        unsigned bits = __ballot_sync(0xffffffffu, in);
        if (!have_first && bits) { first_idx = base + __ffs((int)bits) - 1; have_first = true; }
        if (in) {
            int pos = cnt + __popc(bits & ((1u << lane) - 1u));
            if (pos < NSAMPLE) gout[pos] = n;
        }
        cnt += __popc(bits);
        if (cnt >= NSAMPLE) break;
    }
    if (cnt < NSAMPLE) {
        for (int pos = cnt + lane; pos < NSAMPLE; pos += 32) gout[pos] = first_idx;
    }
}

// ---------------- layer0: gather + concat + linear (IC=67, OC=64), f32x2 ------
__global__ __launch_bounds__(256) void layer0_kernel(const float* __restrict__ xyz,
                                                     const float* __restrict__ points,
                                                     const float* __restrict__ w,
                                                     const float* __restrict__ bias,
                                                     float* __restrict__ y)
{
    __shared__ u64   sw2[64*64];   // [c][oc], weight duplicated into both halves
    __shared__ float sw3[3*64];    // first 3 input channels (rel xyz), scalar
    __shared__ float sb[64];
    for (int i = threadIdx.x; i < 64*64; i += 256) {
        int c = i >> 6, oc = i & 63;
        float v = w[oc*67 + 3 + c];
        sw2[i] = pack2(v, v);
    }
    if (threadIdx.x < 3*64) {
        int kk = threadIdx.x >> 6, oc = threadIdx.x & 63;
        sw3[threadIdx.x] = w[oc*67 + kk];
    }
    if (threadIdx.x < 64) sb[threadIdx.x] = bias[threadIdx.x];
    __syncthreads();

    const int p  = blockIdx.x*256 + threadIdx.x;   // pair index
    const int r0 = p*2, r1 = r0 + 1;
    const int center = r0 >> 5;
    const int b = center >> 10;
    const int n0 = g_gidx[r0];
    const int n1 = g_gidx[r1];
    const float* pp0 = points + ((size_t)(b*NPTS + n0))*CIN;
    const float* pp1 = points + ((size_t)(b*NPTS + n1))*CIN;
    const float cx = g_new_xyz[center*3+0];
    const float cy = g_new_xyz[center*3+1];
    const float cz = g_new_xyz[center*3+2];
    const float x0a = xyz[(size_t)(b*NPTS+n0)*3+0] - cx;
    const float x1a = xyz[(size_t)(b*NPTS+n0)*3+1] - cy;
    const float x2a = xyz[(size_t)(b*NPTS+n0)*3+2] - cz;
    const float x0b = xyz[(size_t)(b*NPTS+n1)*3+0] - cx;
    const float x1b = xyz[(size_t)(b*NPTS+n1)*3+1] - cy;
    const float x2b = xyz[(size_t)(b*NPTS+n1)*3+2] - cz;

    u64 acc[64];
#pragma unroll
    for (int j = 0; j < 64; j++) {
        float a = sb[j], bvl = sb[j];
        a   = fmaf(sw3[j],       x0a, a);
        a   = fmaf(sw3[64+j],    x1a, a);
        a   = fmaf(sw3[128+j],   x2a, a);
        bvl = fmaf(sw3[j],       x0b, bvl);
        bvl = fmaf(sw3[64+j],    x1b, bvl);
        bvl = fmaf(sw3[128+j],   x2b, bvl);
        acc[j] = pack2(a, bvl);
    }

    float a0 = pp0[0], a1 = pp1[0];
#pragma unroll 1
    for (int c = 0; c < CIN; c++) {
        int cn = (c + 1 < CIN) ? c + 1 : c;
        float na0 = pp0[cn], na1 = pp1[cn];
        u64 xa = pack2(a0, a1);
        const ulonglong2* wrow = (const ulonglong2*)(sw2 + c*64);
#pragma unroll
        for (int q = 0; q < 32; q++) {
            ulonglong2 wv = wrow[q];
            fma2(acc[2*q],   wv.x, xa);
            fma2(acc[2*q+1], wv.y, xa);
        }
        a0 = na0; a1 = na1;
    }
#pragma unroll
    for (int j = 0; j < 64; j++) {
        float lo, hi; unpack2(acc[j], lo, hi);
        ((float2*)(y + (size_t)j*R_TOTAL))[p] = make_float2(lo, hi);
    }
}

// ---------------- mlp1: BN(prev)+relu input, linear 64->64, f32x2 -------------
__global__ __launch_bounds__(256) void mlp_layer_kernel(const float* __restrict__ x,
                                                        const float* __restrict__ w,
                                                        const float* __restrict__ bias,
                                                        float* __restrict__ y)
{
    __shared__ u64   sw2[64*64];
    __shared__ float sb[64];
    __shared__ float ssc[64], ssh[64];
    for (int i = threadIdx.x; i < 64*64; i += 256) {
        int c = i >> 6, oc = i & 63;
        float v = w[oc*64 + c];
        sw2[i] = pack2(v, v);
    }
    if (threadIdx.x < 64) {
        sb[threadIdx.x]  = bias[threadIdx.x];
        ssc[threadIdx.x] = g_scale[threadIdx.x];
        ssh[threadIdx.x] = g_shift[threadIdx.x];
    }
    __syncthreads();

    const int p = blockIdx.x*256 + threadIdx.x;    // pair index
    const float2* x2 = (const float2*)x;

    u64 acc[64];
#pragma unroll
    for (int j = 0; j < 64; j++) acc[j] = pack2(sb[j], sb[j]);

    float2 cur = x2[p];
#pragma unroll 1
    for (int c = 0; c < 64; c++) {
        int cn = (c + 1 < 64) ? c + 1 : c;
        float2 nxt = x2[(size_t)cn*RPAIRS + p];
        float s = ssc[c], h = ssh[c];
        float a0 = fmaxf(fmaf(cur.x, s, h), 0.0f);
        float a1 = fmaxf(fmaf(cur.y, s, h), 0.0f);
        u64 xa = pack2(a0, a1);
        const ulonglong2* wrow = (const ulonglong2*)(sw2 + c*64);
#pragma unroll
        for (int q = 0; q < 32; q++) {
            ulonglong2 wv = wrow[q];
            fma2(acc[2*q],   wv.x, xa);
            fma2(acc[2*q+1], wv.y, xa);
        }
        cur = nxt;
    }
#pragma unroll
    for (int j = 0; j < 64; j++) {
        float lo, hi; unpack2(acc[j], lo, hi);
        ((float2*)(y + (size_t)j*R_TOTAL))[p] = make_float2(lo, hi);
    }
}

// ---------------- mlp2 fused: linear 64->128 (half per blockIdx.y) + in-register
// stats (sum/sumsq -> atomics) + per-center raw max/min pooling (no y write) ----
__global__ __launch_bounds__(256) void mlp2_pool_kernel(const float* __restrict__ x,
                                                        const float* __restrict__ w,
                                                        const float* __restrict__ bias)
{
    __shared__ u64   sw2[64*64];
    __shared__ float sb[64];
    __shared__ float ssc[64], ssh[64];
    const int ocb = blockIdx.y * 64;
    for (int i = threadIdx.x; i < 64*64; i += 256) {
        int c = i >> 6, oc = i & 63;
        float v = w[(ocb + oc)*64 + c];
        sw2[i] = pack2(v, v);
    }
    if (threadIdx.x < 64) {
        sb[threadIdx.x]  = bias[ocb + threadIdx.x];
        ssc[threadIdx.x] = g_scale[threadIdx.x];
        ssh[threadIdx.x] = g_shift[threadIdx.x];
    }
    __syncthreads();

    const int p    = blockIdx.x*256 + threadIdx.x;  // pair index (rows 2p,2p+1)
    const int lane = threadIdx.x & 31;
    const float2* x2 = (const float2*)x;

    u64 acc[64];
#pragma unroll
    for (int j = 0; j < 64; j++) acc[j] = pack2(sb[j], sb[j]);

    float2 cur = x2[p];
#pragma unroll 1
    for (int c = 0; c < 64; c++) {
        int cn = (c + 1 < 64) ? c + 1 : c;
        float2 nxt = x2[(size_t)cn*RPAIRS + p];
        float s = ssc[c], h = ssh[c];
        float a0 = fmaxf(fmaf(cur.x, s, h), 0.0f);
        float a1 = fmaxf(fmaf(cur.y, s, h), 0.0f);
        u64 xa = pack2(a0, a1);
        const ulonglong2* wrow = (const ulonglong2*)(sw2 + c*64);
#pragma unroll
        for (int q = 0; q < 32; q++) {
            ulonglong2 wv = wrow[q];
            fma2(acc[2*q],   wv.x, xa);
            fma2(acc[2*q+1], wv.y, xa);
        }
        cur = nxt;
    }

    // ---- epilogue: 16-lane (one center) max/min butterflies + warp sum/sumsq ----
    float pm[4], pmn[4];       // this lane's retained channels: j = (lane&15)+16k
    float s2[2], q2[2];        // this lane's retained sums:      j = lane + 32m
#pragma unroll
    for (int j = 0; j < 64; j++) {
        float lo, hi; unpack2(acc[j], lo, hi);
        float mx = fmaxf(lo, hi);
        float mn = fminf(lo, hi);
#pragma unroll
        for (int off = 8; off; off >>= 1) {
            mx = fmaxf(mx, __shfl_xor_sync(0xffffffffu, mx, off));
            mn = fminf(mn, __shfl_xor_sync(0xffffffffu, mn, off));
        }
        float s = lo + hi;
        float q = fmaf(lo, lo, hi*hi);
#pragma unroll
        for (int off = 16; off; off >>= 1) {
            s += __shfl_xor_sync(0xffffffffu, s, off);
            q += __shfl_xor_sync(0xffffffffu, q, off);
        }
        if ((j & 15) == (lane & 15)) { pm[j >> 4] = mx; pmn[j >> 4] = mn; }
        if ((j & 31) == lane)        { s2[j >> 5] = s;  q2[j >> 5] = q; }
    }

    const int cen = p >> 4;   // 16 consecutive pairs = 32 rows = one center
#pragma unroll
    for (int kq = 0; kq < 4; kq++) {
        int ch = ocb + (lane & 15) + kq*16;
        g_pmax[(size_t)cen*128 + ch] = pm[kq];
        g_pmin[(size_t)cen*128 + ch] = pmn[kq];
    }
#pragma unroll
    for (int m = 0; m < 2; m++) {
        int ch = ocb + lane + 32*m;
        atomicAdd(&g_sums[ch],       s2[m]);
        atomicAdd(&g_sums[128 + ch], q2[m]);
    }
}

// ---------------- BN stats (layers 0,1): float4 grid-stride ----------------
__global__ __launch_bounds__(256) void stats_kernel(const float* __restrict__ y)
{
    const int c = blockIdx.y;
    const float4* p = (const float4*)(y + (size_t)c*R_TOTAL);
    const int n4 = R_TOTAL / 4;
    float s = 0.f, ss = 0.f;
    for (int i = blockIdx.x*256 + threadIdx.x; i < n4; i += gridDim.x*256) {
        float4 v = p[i];
        s += v.x; ss = fmaf(v.x, v.x, ss);
        s += v.y; ss = fmaf(v.y, v.y, ss);
        s += v.z; ss = fmaf(v.z, v.z, ss);
        s += v.w; ss = fmaf(v.w, v.w, ss);
    }
#pragma unroll
    for (int off = 16; off; off >>= 1) {
        s  += __shfl_down_sync(0xffffffffu, s,  off);
        ss += __shfl_down_sync(0xffffffffu, ss, off);
    }
    __shared__ float sh[16];
    const int lane = threadIdx.x & 31, wid = threadIdx.x >> 5;
    if (lane == 0) { sh[wid] = s; sh[8 + wid] = ss; }
    __syncthreads();
    if (threadIdx.x == 0) {
        float ts = 0.f, tss = 0.f;
#pragma unroll
        for (int k = 0; k < 8; k++) { ts += sh[k]; tss += sh[8+k]; }
        atomicAdd(&g_sums[c], ts);
        atomicAdd(&g_sums[128 + c], tss);
    }
}

// ---------------- finalize BN: scale/shift, reset sums ----------------
__global__ void finalize_kernel(const float* __restrict__ gamma,
                                const float* __restrict__ beta, int OC)
{
    const int c = threadIdx.x;   // 128 threads
    const float s  = g_sums[c];
    const float ss = g_sums[128 + c];
    if (c < OC) {
        const float inv = 1.0f / (float)R_TOTAL;
        float mu  = s * inv;
        float var = ss * inv - mu*mu;
        float sc  = gamma[c] / sqrtf(var + 1e-5f);
        g_scale[c] = sc;
        g_shift[c] = fmaf(-mu, sc, beta[c]);
    }
    g_sums[c] = 0.f;
    g_sums[128 + c] = 0.f;
}

// ---------------- final: pick max/min by sign(scale), BN + relu (8 MB) --------
__global__ __launch_bounds__(256) void final_kernel(float* __restrict__ out)
{
    const int idx = blockIdx.x*256 + threadIdx.x;     // NCENT*128
    const int ch = idx & 127;
    const float sc = g_scale[ch], sh = g_shift[ch];
    float v = (sc >= 0.0f) ? g_pmax[idx] : g_pmin[idx];
    out[(size_t)BATCH*NPOINT*3 + idx] = fmaxf(fmaf(v, sc, sh), 0.0f);
}

// ---------------- launcher ----------------
extern "C" void kernel_launch(void* const* d_in, const int* in_sizes, int n_in,
                              void* d_out, int out_size)
{
    (void)in_sizes; (void)n_in; (void)out_size;
    const float* xyz    = (const float*)d_in[0];
    const float* points = (const float*)d_in[1];
    const float* w0  = (const float*)d_in[2];
    const float* b0  = (const float*)d_in[3];
    const float* gm0 = (const float*)d_in[4];
    const float* bt0 = (const float*)d_in[5];
    const float* w1  = (const float*)d_in[6];
    const float* b1  = (const float*)d_in[7];
    const float* gm1 = (const float*)d_in[8];
    const float* bt1 = (const float*)d_in[9];
    const float* w2  = (const float*)d_in[10];
    const float* b2  = (const float*)d_in[11];
    const float* gm2 = (const float*)d_in[12];
    const float* bt2 = (const float*)d_in[13];
    float* out = (float*)d_out;

    float *bufA = nullptr, *bufB = nullptr;
    cudaGetSymbolAddress((void**)&bufA, g_bufA);
    cudaGetSymbolAddress((void**)&bufB, g_bufB);

    fps_kernel<<<BATCH, 512>>>(xyz, out);
    ballquery_kernel<<<NCENT/4, 128>>>(xyz);

    layer0_kernel<<<RPAIRS/256, 256>>>(xyz, points, w0, b0, bufA);
    stats_kernel<<<dim3(32, 64), 256>>>(bufA);
    finalize_kernel<<<1, 128>>>(gm0, bt0, 64);

    mlp_layer_kernel<<<RPAIRS/256, 256>>>(bufA, w1, b1, bufB);
    stats_kernel<<<dim3(32, 64), 256>>>(bufB);
    finalize_kernel<<<1, 128>>>(gm1, bt1, 64);

    mlp2_pool_kernel<<<dim3(RPAIRS/256, 2), 256>>>(bufB, w2, b2);
    finalize_kernel<<<1, 128>>>(gm2, bt2, 128);

    final_kernel<<<(NCENT*128)/256, 256>>>(out);
}